// round 10
// baseline (speedup 1.0000x reference)
#include <cuda_runtime.h>
#include <math.h>
#include <stdint.h>

#define T_DIM 4096
#define D_DIM 1024
#define NH    16
#define HD    64
#define L_ROT 32

// Scratch (no allocations allowed -> __device__ globals)
__device__ float g_Q[NH * T_DIM * HD];
__device__ float g_K[NH * T_DIM * HD];
__device__ float g_V[NH * T_DIM * HD];
__device__ float g_vals[T_DIM * D_DIM];

// ---------------------------------------------------------------------------
// helpers
// ---------------------------------------------------------------------------
__device__ __forceinline__ unsigned f2tf(float f) {
    unsigned u;
    asm("cvt.rna.tf32.f32 %0, %1;" : "=r"(u) : "f"(f));
    return u;
}

__device__ __forceinline__ uint32_t smem_u32(const void* p) {
    uint32_t a;
    asm("{ .reg .u64 t; cvta.to.shared.u64 t, %1; cvt.u32.u64 %0, t; }" : "=r"(a) : "l"(p));
    return a;
}

// D += A(16x8, row) * B(8x8, col);  tf32 in, f32 accum
__device__ __forceinline__ void mma8(float* d, const unsigned* a, unsigned b0, unsigned b1) {
    asm volatile(
        "mma.sync.aligned.m16n8k8.row.col.f32.tf32.tf32.f32 "
        "{%0,%1,%2,%3}, {%4,%5,%6,%7}, {%8,%9}, {%0,%1,%2,%3};"
        : "+f"(d[0]), "+f"(d[1]), "+f"(d[2]), "+f"(d[3])
        : "r"(a[0]), "r"(a[1]), "r"(a[2]), "r"(a[3]), "r"(b0), "r"(b1));
}

#define CP_ASYNC16(dst_u32, src_ptr) \
    asm volatile("cp.async.cg.shared.global [%0], [%1], 16;" :: "r"(dst_u32), "l"(src_ptr))
#define CP_COMMIT() asm volatile("cp.async.commit_group;" ::: "memory")

// ---------------------------------------------------------------------------
// tf32 GEMM via mma.sync, cp.async double-buffered.
// C = A (MxK row-major) * B^T (B is NxK row-major)
// mode 0: C[m*N + n] ; mode 1: C[((n>>6)*M + m)*64 + (n&63)]  (per-head layout)
// BM=BN=128, BK=32, 256 threads, warp grid 2(M)x4(N), warp tile 64x32.
// SMEM raw f32, pad 36 (fragment loads conflict-free); cvt at fragment load.
// ---------------------------------------------------------------------------
#define GEMM_SMEM_FLOATS (2 * 2 * 128 * 36)   // 18432 floats = 73728 B

__global__ __launch_bounds__(256) void gemm_tf32(
    const float* __restrict__ A, const float* __restrict__ B,
    float* __restrict__ C, int M, int N, int K, int mode)
{
    extern __shared__ float smf[];
    float* Asb[2] = { smf,        smf + 9216 };
    float* Bsb[2] = { smf + 4608, smf + 13824 };

    const int tid = threadIdx.x;
    const int bm = blockIdx.y * 128;
    const int bn = blockIdx.x * 128;
    const int w = tid >> 5, lane = tid & 31;
    const int g = lane >> 2, tg = lane & 3;
    const int wm = (w >> 2) * 64;   // warp M offset (0 or 64)
    const int wn = (w & 3) * 32;    // warp N offset (0..96)

    const int lr = tid >> 1;          // 0..127: row
    const int lc = (tid & 1) * 16;    // 0 or 16: col base (16 floats per thread)

    const float* arow = A + (size_t)(bm + lr) * K + lc;
    const float* brow = B + (size_t)(bn + lr) * K + lc;

    float cf[4][4][4];
#pragma unroll
    for (int mt = 0; mt < 4; mt++)
#pragma unroll
        for (int nt = 0; nt < 4; nt++)
#pragma unroll
            for (int r = 0; r < 4; r++) cf[mt][nt][r] = 0.f;

    // prologue: stage 0
    {
        uint32_t ad = smem_u32(&Asb[0][lr * 36 + lc]);
        uint32_t bd = smem_u32(&Bsb[0][lr * 36 + lc]);
#pragma unroll
        for (int s2 = 0; s2 < 4; s2++) {
            CP_ASYNC16(ad + s2 * 16, arow + s2 * 4);
            CP_ASYNC16(bd + s2 * 16, brow + s2 * 4);
        }
        CP_COMMIT();
    }

    const int NC = K / 32;
    for (int c = 0; c < NC; c++) {
        const int buf = c & 1;
        if (c + 1 < NC) {
            const float* ap = arow + (c + 1) * 32;
            const float* bp = brow + (c + 1) * 32;
            uint32_t ad = smem_u32(&Asb[buf ^ 1][lr * 36 + lc]);
            uint32_t bd = smem_u32(&Bsb[buf ^ 1][lr * 36 + lc]);
#pragma unroll
            for (int s2 = 0; s2 < 4; s2++) {
                CP_ASYNC16(ad + s2 * 16, ap + s2 * 4);
                CP_ASYNC16(bd + s2 * 16, bp + s2 * 4);
            }
            CP_COMMIT();
            asm volatile("cp.async.wait_group 1;" ::: "memory");
        } else {
            asm volatile("cp.async.wait_group 0;" ::: "memory");
        }
        __syncthreads();

        const float* As_ = Asb[buf];
        const float* Bs_ = Bsb[buf];
#pragma unroll
        for (int s = 0; s < 4; s++) {
            unsigned af[4][4];
#pragma unroll
            for (int mt = 0; mt < 4; mt++) {
                int r = wm + mt * 16;
                af[mt][0] = f2tf(As_[(r + g) * 36 + s * 8 + tg]);
                af[mt][1] = f2tf(As_[(r + g + 8) * 36 + s * 8 + tg]);
                af[mt][2] = f2tf(As_[(r + g) * 36 + s * 8 + tg + 4]);
                af[mt][3] = f2tf(As_[(r + g + 8) * 36 + s * 8 + tg + 4]);
            }
#pragma unroll
            for (int nt = 0; nt < 4; nt++) {
                int cn = wn + nt * 8 + g;
                unsigned b0 = f2tf(Bs_[cn * 36 + s * 8 + tg]);
                unsigned b1 = f2tf(Bs_[cn * 36 + s * 8 + tg + 4]);
#pragma unroll
                for (int mt = 0; mt < 4; mt++) mma8(cf[mt][nt], af[mt], b0, b1);
            }
        }
        __syncthreads();
    }

#pragma unroll
    for (int mt = 0; mt < 4; mt++) {
        int m = bm + wm + mt * 16 + g;
#pragma unroll
        for (int nt = 0; nt < 4; nt++) {
            int n = bn + wn + nt * 8 + 2 * tg;
            float2 lo = make_float2(cf[mt][nt][0], cf[mt][nt][1]);
            float2 hi = make_float2(cf[mt][nt][2], cf[mt][nt][3]);
            if (mode == 0) {
                *(float2*)&C[(size_t)m * N + n] = lo;
                *(float2*)&C[(size_t)(m + 8) * N + n] = hi;
            } else {
                int h = n >> 6, d = n & 63;
                *(float2*)&C[(size_t)(h * M + m) * 64 + d] = lo;
                *(float2*)&C[(size_t)(h * M + m + 8) * 64 + d] = hi;
            }
        }
    }
}

// ---------------------------------------------------------------------------
// fused RoPE: first 32 dims of each head, q/k/v in one launch (ROT_SCALE=1)
// ---------------------------------------------------------------------------
__global__ void rope_kernel(float* __restrict__ bq, float* __restrict__ bk,
                            float* __restrict__ bv, const float* __restrict__ freqs)
{
    int idx = blockIdx.x * blockDim.x + threadIdx.x;  // NH*T_DIM*16 total
    int p = idx & 15;
    int t = (idx >> 4) & (T_DIM - 1);
    int h = idx >> 16;
    if (h >= NH) return;
    float* buf = (blockIdx.y == 0) ? bq : (blockIdx.y == 1) ? bk : bv;
    float* x = buf + ((size_t)h * T_DIM + t) * HD;
    float a = x[p];
    float b = x[p + 16];
    float f0 = freqs[t * L_ROT + p];
    float f1 = freqs[t * L_ROT + p + 16];
    x[p]      = a * cosf(f0) - b * sinf(f0);
    x[p + 16] = b * cosf(f1) + a * sinf(f1);
}

// ---------------------------------------------------------------------------
// Flash attention, tf32 mma.sync. Block = 256 threads (8 warps), 128 q rows,
// 64-key j-tiles. Warp w owns i-rows [w*16, w*16+16).
// K [j][k] pad 68 (B-frags CF), V^T [c][j] pad 65, S/P [i][j] pad 69.
// it reversed so heavy causal blocks launch first.
// ---------------------------------------------------------------------------
#define KS_PAD 68
#define VS_PAD 65
#define SS_PAD 69
#define ATT_SMEM_FLOATS (64*KS_PAD + 64*VS_PAD + 128*SS_PAD + 128*3 + 256*2)

__global__ __launch_bounds__(256) void attn_mma(
    const float* __restrict__ Qb, const float* __restrict__ Kb,
    const float* __restrict__ Vb, float* __restrict__ vals)
{
    extern __shared__ float smf[];
    float* Ks   = smf;                       // [64][68]
    float* Vs   = Ks + 64 * KS_PAD;          // [64][65]  (V transposed: [c][j])
    float* Ss   = Vs + 64 * VS_PAD;          // [128][69]
    float* mrow = Ss + 128 * SS_PAD;         // [128]
    float* lrow = mrow + 128;                // [128]
    float* crow = lrow + 128;                // [128]
    float* pmax = crow + 128;                // [2][128]
    float* psum = pmax + 256;                // [2][128]

    const int h = blockIdx.y;
    const int it = gridDim.x - 1 - blockIdx.x;   // heavy blocks first
    const int tid = threadIdx.x;
    const int w = tid >> 5, lane = tid & 31;
    const int g = lane >> 2, tg = lane & 3;
    const int stripe = w * 16;

    // Q fragments in registers, pre-scaled by 1/sqrt(64)=0.125, tf32
    const float* Qh = Qb + ((size_t)h * T_DIM + it * 128) * HD;
    unsigned qf[8][4];
#pragma unroll
    for (int s = 0; s < 8; s++) {
        int r0 = (stripe + g) * HD, r1 = (stripe + g + 8) * HD;
        qf[s][0] = f2tf(Qh[r0 + s * 8 + tg] * 0.125f);
        qf[s][1] = f2tf(Qh[r1 + s * 8 + tg] * 0.125f);
        qf[s][2] = f2tf(Qh[r0 + s * 8 + tg + 4] * 0.125f);
        qf[s][3] = f2tf(Qh[r1 + s * 8 + tg + 4] * 0.125f);
    }

    float of[8][4];
#pragma unroll
    for (int nt = 0; nt < 8; nt++)
#pragma unroll
        for (int r = 0; r < 4; r++) of[nt][r] = 0.f;

    if (tid < 128) { mrow[tid] = -INFINITY; lrow[tid] = 0.f; }

    const float* Kh = Kb + (size_t)h * T_DIM * HD;
    const float* Vh = Vb + (size_t)h * T_DIM * HD;

    const int row = tid & 127, half = tid >> 7;
    const int cbeg = half * 32;

    const int njt = 2 * it + 2;
    for (int jt = 0; jt < njt; jt++) {
        __syncthreads();   // (a) prev-iter reads of Ks/Vs/Ss done; init visible
        // --- load K tile (tf32) and V tile transposed (tf32) ---
#pragma unroll
        for (int p = 0; p < 4; p++) {
            int idx = tid + p * 256;
            int j = idx >> 4, c4 = idx & 15;
            float4 kf = *(const float4*)&Kh[(size_t)(jt * 64 + j) * HD + 4 * c4];
            float4 kt = make_float4(__uint_as_float(f2tf(kf.x)), __uint_as_float(f2tf(kf.y)),
                                    __uint_as_float(f2tf(kf.z)), __uint_as_float(f2tf(kf.w)));
            *(float4*)&Ks[j * KS_PAD + 4 * c4] = kt;
            float4 vf = *(const float4*)&Vh[(size_t)(jt * 64 + j) * HD + 4 * c4];
            Vs[(4 * c4 + 0) * VS_PAD + j] = __uint_as_float(f2tf(vf.x));
            Vs[(4 * c4 + 1) * VS_PAD + j] = __uint_as_float(f2tf(vf.y));
            Vs[(4 * c4 + 2) * VS_PAD + j] = __uint_as_float(f2tf(vf.z));
            Vs[(4 * c4 + 3) * VS_PAD + j] = __uint_as_float(f2tf(vf.w));
        }
        __syncthreads();   // (b) tiles ready

        // --- S = Q K^T (already scaled) ---
#pragma unroll
        for (int nt = 0; nt < 8; nt++) {
            float sf[4] = {0.f, 0.f, 0.f, 0.f};
#pragma unroll
            for (int s = 0; s < 8; s++) {
                unsigned b0 = __float_as_uint(Ks[(nt * 8 + g) * KS_PAD + s * 8 + tg]);
                unsigned b1 = __float_as_uint(Ks[(nt * 8 + g) * KS_PAD + s * 8 + tg + 4]);
                mma8(sf, qf[s], b0, b1);
            }
            int r0 = stripe + g, col = nt * 8 + 2 * tg;
            Ss[r0 * SS_PAD + col]           = sf[0];
            Ss[r0 * SS_PAD + col + 1]       = sf[1];
            Ss[(r0 + 8) * SS_PAD + col]     = sf[2];
            Ss[(r0 + 8) * SS_PAD + col + 1] = sf[3];
        }
        __syncthreads();   // (c) S ready

        // --- softmax: 256 threads, half-row each ---
        const int jmaxl = it * 128 + row - jt * 64;   // local causal limit
        float lmax = -INFINITY;
#pragma unroll
        for (int jj = 0; jj < 32; jj++) {
            int c = cbeg + jj;
            if (c <= jmaxl) lmax = fmaxf(lmax, Ss[row * SS_PAD + c]);
        }
        pmax[half * 128 + row] = lmax;
        __syncthreads();   // (d) partial maxima ready

        float mold = mrow[row];
        float mnew = fmaxf(mold, fmaxf(pmax[row], pmax[128 + row]));
        float corrv = __expf(mold - mnew);
        float ls = 0.f;
#pragma unroll
        for (int jj = 0; jj < 32; jj++) {
            int c = cbeg + jj;
            float p = (c <= jmaxl) ? __expf(Ss[row * SS_PAD + c] - mnew) : 0.f;
            ls += p;
            Ss[row * SS_PAD + c] = __uint_as_float(f2tf(p));
        }
        psum[half * 128 + row] = ls;
        if (half == 0) crow[row] = corrv;
        __syncthreads();   // (e) P, corr, partial sums ready

        if (half == 0) {
            lrow[row] = lrow[row] * corrv + psum[row] + psum[128 + row];
            mrow[row] = mnew;
        }

        // --- rescale O, then O += P V ---
        float cr0 = crow[stripe + g], cr1 = crow[stripe + g + 8];
#pragma unroll
        for (int nt = 0; nt < 8; nt++) {
            of[nt][0] *= cr0; of[nt][1] *= cr0;
            of[nt][2] *= cr1; of[nt][3] *= cr1;
        }
#pragma unroll
        for (int s = 0; s < 8; s++) {
            unsigned af[4];
            af[0] = __float_as_uint(Ss[(stripe + g) * SS_PAD + s * 8 + tg]);
            af[1] = __float_as_uint(Ss[(stripe + g + 8) * SS_PAD + s * 8 + tg]);
            af[2] = __float_as_uint(Ss[(stripe + g) * SS_PAD + s * 8 + tg + 4]);
            af[3] = __float_as_uint(Ss[(stripe + g + 8) * SS_PAD + s * 8 + tg + 4]);
#pragma unroll
            for (int nt = 0; nt < 8; nt++) {
                unsigned b0 = __float_as_uint(Vs[(nt * 8 + g) * VS_PAD + s * 8 + tg]);
                unsigned b1 = __float_as_uint(Vs[(nt * 8 + g) * VS_PAD + s * 8 + tg + 4]);
                mma8(of[nt], af, b0, b1);
            }
        }
    }

    // --- epilogue: O /= l, write [t][h*64+c] ---
    __syncthreads();
    if (tid < 128) crow[tid] = 1.f / lrow[tid];
    __syncthreads();
    float i0 = crow[stripe + g], i1 = crow[stripe + g + 8];
    int qi0 = it * 128 + stripe + g;
#pragma unroll
    for (int nt = 0; nt < 8; nt++) {
        int col = h * 64 + nt * 8 + 2 * tg;
        *(float2*)&vals[(size_t)qi0 * D_DIM + col] =
            make_float2(of[nt][0] * i0, of[nt][1] * i0);
        *(float2*)&vals[(size_t)(qi0 + 8) * D_DIM + col] =
            make_float2(of[nt][2] * i1, of[nt][3] * i1);
    }
}

// ---------------------------------------------------------------------------
extern "C" void kernel_launch(void* const* d_in, const int* in_sizes, int n_in,
                              void* d_out, int out_size)
{
    const float* q     = (const float*)d_in[0];
    const float* k     = (const float*)d_in[1];
    const float* v     = (const float*)d_in[2];
    // d_in[3] = mask (causal, static -> unused)
    const float* freqs = (const float*)d_in[4];
    const float* wq    = (const float*)d_in[5];
    const float* wk    = (const float*)d_in[6];
    const float* wv    = (const float*)d_in[7];
    const float* wo    = (const float*)d_in[8];
    float* out = (float*)d_out;

    float *gq, *gk, *gv, *gvals;
    cudaGetSymbolAddress((void**)&gq, g_Q);
    cudaGetSymbolAddress((void**)&gk, g_K);
    cudaGetSymbolAddress((void**)&gv, g_V);
    cudaGetSymbolAddress((void**)&gvals, g_vals);

    const int att_smem  = ATT_SMEM_FLOATS * sizeof(float);    // 72960 B
    const int gemm_smem = GEMM_SMEM_FLOATS * sizeof(float);   // 73728 B
    cudaFuncSetAttribute(attn_mma, cudaFuncAttributeMaxDynamicSharedMemorySize, att_smem);
    cudaFuncSetAttribute(gemm_tf32, cudaFuncAttributeMaxDynamicSharedMemorySize, gemm_smem);

    dim3 ggrid(D_DIM / 128, T_DIM / 128);  // (8, 32)

    gemm_tf32<<<ggrid, 256, gemm_smem>>>(q, wq, gq, T_DIM, D_DIM, D_DIM, 1);
    gemm_tf32<<<ggrid, 256, gemm_smem>>>(k, wk, gk, T_DIM, D_DIM, D_DIM, 1);
    gemm_tf32<<<ggrid, 256, gemm_smem>>>(v, wv, gv, T_DIM, D_DIM, D_DIM, 1);

    rope_kernel<<<dim3(NH * T_DIM * 16 / 256, 3), 256>>>(gq, gk, gv, freqs);

    attn_mma<<<dim3(T_DIM / 128, NH), 256, att_smem>>>(gq, gk, gv, gvals);

    gemm_tf32<<<ggrid, 256, gemm_smem>>>(gvals, wo, out, T_DIM, D_DIM, D_DIM, 0);
}

// round 11
// speedup vs baseline: 1.0850x; 1.0850x over previous
#include <cuda_runtime.h>
#include <math.h>
#include <stdint.h>

#define T_DIM 4096
#define D_DIM 1024
#define NH    16
#define HD    64
#define L_ROT 32

// Scratch (no allocations allowed -> __device__ globals)
__device__ float g_Q[NH * T_DIM * HD];
__device__ float g_K[NH * T_DIM * HD];
__device__ float g_V[NH * T_DIM * HD];
__device__ float g_vals[T_DIM * D_DIM];

// ---------------------------------------------------------------------------
// helpers
// ---------------------------------------------------------------------------
__device__ __forceinline__ unsigned f2tf(float f) {
    unsigned u;
    asm("cvt.rna.tf32.f32 %0, %1;" : "=r"(u) : "f"(f));
    return u;
}

__device__ __forceinline__ uint32_t smem_u32(const void* p) {
    uint32_t a;
    asm("{ .reg .u64 t; cvta.to.shared.u64 t, %1; cvt.u32.u64 %0, t; }" : "=r"(a) : "l"(p));
    return a;
}

// D += A(16x8, row) * B(8x8, col);  tf32 in, f32 accum
__device__ __forceinline__ void mma8(float* d, const unsigned* a, unsigned b0, unsigned b1) {
    asm volatile(
        "mma.sync.aligned.m16n8k8.row.col.f32.tf32.tf32.f32 "
        "{%0,%1,%2,%3}, {%4,%5,%6,%7}, {%8,%9}, {%0,%1,%2,%3};"
        : "+f"(d[0]), "+f"(d[1]), "+f"(d[2]), "+f"(d[3])
        : "r"(a[0]), "r"(a[1]), "r"(a[2]), "r"(a[3]), "r"(b0), "r"(b1));
}

#define CP_ASYNC16(dst_u32, src_ptr) \
    asm volatile("cp.async.cg.shared.global [%0], [%1], 16;" :: "r"(dst_u32), "l"(src_ptr))
#define CP_COMMIT() asm volatile("cp.async.commit_group;" ::: "memory")

// ---------------------------------------------------------------------------
// tf32 GEMM via mma.sync, cp.async double-buffered + cooperative cvt pass.
// C = A (MxK row-major) * B^T (B is NxK row-major)
// mode 0: C[m*N + n] (fp32)          -- final projection output
// mode 1: C[((n>>6)*M + m)*64 + (n&63)] per-head layout, tf32-ROUNDED output
// BM=BN=128, BK=32, 256 threads, warp grid 2(M)x4(N), warp tile 64x32.
// ---------------------------------------------------------------------------
#define GEMM_SMEM_FLOATS (2 * 2 * 128 * 36)   // 18432 floats = 73728 B

__global__ __launch_bounds__(256) void gemm_tf32(
    const float* __restrict__ A, const float* __restrict__ B,
    float* __restrict__ C, int M, int N, int K, int mode)
{
    extern __shared__ float smf[];
    float* Asb[2] = { smf,        smf + 9216 };
    float* Bsb[2] = { smf + 4608, smf + 13824 };

    const int tid = threadIdx.x;
    const int bm = blockIdx.y * 128;
    const int bn = blockIdx.x * 128;
    const int w = tid >> 5, lane = tid & 31;
    const int g = lane >> 2, tg = lane & 3;
    const int wm = (w >> 2) * 64;   // warp M offset (0 or 64)
    const int wn = (w & 3) * 32;    // warp N offset (0..96)

    const int lr = tid >> 1;          // 0..127: row
    const int lc = (tid & 1) * 16;    // 0 or 16: col base (16 floats per thread)

    const float* arow = A + (size_t)(bm + lr) * K + lc;
    const float* brow = B + (size_t)(bn + lr) * K + lc;

    float cf[4][4][4];
#pragma unroll
    for (int mt = 0; mt < 4; mt++)
#pragma unroll
        for (int nt = 0; nt < 4; nt++)
#pragma unroll
            for (int r = 0; r < 4; r++) cf[mt][nt][r] = 0.f;

    // prologue: stage 0
    {
        uint32_t ad = smem_u32(&Asb[0][lr * 36 + lc]);
        uint32_t bd = smem_u32(&Bsb[0][lr * 36 + lc]);
#pragma unroll
        for (int s2 = 0; s2 < 4; s2++) {
            CP_ASYNC16(ad + s2 * 16, arow + s2 * 4);
            CP_ASYNC16(bd + s2 * 16, brow + s2 * 4);
        }
        CP_COMMIT();
    }

    const int NC = K / 32;
    for (int c = 0; c < NC; c++) {
        const int buf = c & 1;
        if (c + 1 < NC) {
            const float* ap = arow + (c + 1) * 32;
            const float* bp = brow + (c + 1) * 32;
            uint32_t ad = smem_u32(&Asb[buf ^ 1][lr * 36 + lc]);
            uint32_t bd = smem_u32(&Bsb[buf ^ 1][lr * 36 + lc]);
#pragma unroll
            for (int s2 = 0; s2 < 4; s2++) {
                CP_ASYNC16(ad + s2 * 16, ap + s2 * 4);
                CP_ASYNC16(bd + s2 * 16, bp + s2 * 4);
            }
            CP_COMMIT();
            asm volatile("cp.async.wait_group 1;" ::: "memory");
        } else {
            asm volatile("cp.async.wait_group 0;" ::: "memory");
        }
        __syncthreads();

        // cooperative in-place tf32 rounding: each thread owns exactly the
        // 16+16 floats it cp.async'd (no races), off the MMA critical path
        {
            float* Ab = Asb[buf];
            float* Bb = Bsb[buf];
#pragma unroll
            for (int s2 = 0; s2 < 4; s2++) {
                float4* pa = (float4*)&Ab[lr * 36 + lc + s2 * 4];
                float4 va = *pa;
                va.x = __uint_as_float(f2tf(va.x)); va.y = __uint_as_float(f2tf(va.y));
                va.z = __uint_as_float(f2tf(va.z)); va.w = __uint_as_float(f2tf(va.w));
                *pa = va;
                float4* pb = (float4*)&Bb[lr * 36 + lc + s2 * 4];
                float4 vb = *pb;
                vb.x = __uint_as_float(f2tf(vb.x)); vb.y = __uint_as_float(f2tf(vb.y));
                vb.z = __uint_as_float(f2tf(vb.z)); vb.w = __uint_as_float(f2tf(vb.w));
                *pb = vb;
            }
        }
        __syncthreads();

        const float* As_ = Asb[buf];
        const float* Bs_ = Bsb[buf];
#pragma unroll
        for (int s = 0; s < 4; s++) {
            unsigned af[4][4];
#pragma unroll
            for (int mt = 0; mt < 4; mt++) {
                int r = wm + mt * 16;
                af[mt][0] = __float_as_uint(As_[(r + g) * 36 + s * 8 + tg]);
                af[mt][1] = __float_as_uint(As_[(r + g + 8) * 36 + s * 8 + tg]);
                af[mt][2] = __float_as_uint(As_[(r + g) * 36 + s * 8 + tg + 4]);
                af[mt][3] = __float_as_uint(As_[(r + g + 8) * 36 + s * 8 + tg + 4]);
            }
#pragma unroll
            for (int nt = 0; nt < 4; nt++) {
                int cn = wn + nt * 8 + g;
                unsigned b0 = __float_as_uint(Bs_[cn * 36 + s * 8 + tg]);
                unsigned b1 = __float_as_uint(Bs_[cn * 36 + s * 8 + tg + 4]);
#pragma unroll
                for (int mt = 0; mt < 4; mt++) mma8(cf[mt][nt], af[mt], b0, b1);
            }
        }
        __syncthreads();
    }

#pragma unroll
    for (int mt = 0; mt < 4; mt++) {
        int m = bm + wm + mt * 16 + g;
#pragma unroll
        for (int nt = 0; nt < 4; nt++) {
            int n = bn + wn + nt * 8 + 2 * tg;
            if (mode == 0) {
                // final output: full fp32 accuracy
                *(float2*)&C[(size_t)m * N + n] =
                    make_float2(cf[mt][nt][0], cf[mt][nt][1]);
                *(float2*)&C[(size_t)(m + 8) * N + n] =
                    make_float2(cf[mt][nt][2], cf[mt][nt][3]);
            } else {
                // per-head Q/K/V: tf32-rounded so attention can skip cvt
                int h = n >> 6, d = n & 63;
                float2 lo = make_float2(__uint_as_float(f2tf(cf[mt][nt][0])),
                                        __uint_as_float(f2tf(cf[mt][nt][1])));
                float2 hi = make_float2(__uint_as_float(f2tf(cf[mt][nt][2])),
                                        __uint_as_float(f2tf(cf[mt][nt][3])));
                *(float2*)&C[(size_t)(h * M + m) * 64 + d] = lo;
                *(float2*)&C[(size_t)(h * M + m + 8) * 64 + d] = hi;
            }
        }
    }
}

// ---------------------------------------------------------------------------
// fused RoPE: first 32 dims of each head, q/k/v in one launch (ROT_SCALE=1).
// Writes tf32-rounded values to keep attention inputs exactly tf32.
// ---------------------------------------------------------------------------
__global__ void rope_kernel(float* __restrict__ bq, float* __restrict__ bk,
                            float* __restrict__ bv, const float* __restrict__ freqs)
{
    int idx = blockIdx.x * blockDim.x + threadIdx.x;  // NH*T_DIM*16 total
    int p = idx & 15;
    int t = (idx >> 4) & (T_DIM - 1);
    int h = idx >> 16;
    if (h >= NH) return;
    float* buf = (blockIdx.y == 0) ? bq : (blockIdx.y == 1) ? bk : bv;
    float* x = buf + ((size_t)h * T_DIM + t) * HD;
    float a = x[p];
    float b = x[p + 16];
    float f0 = freqs[t * L_ROT + p];
    float f1 = freqs[t * L_ROT + p + 16];
    x[p]      = __uint_as_float(f2tf(a * cosf(f0) - b * sinf(f0)));
    x[p + 16] = __uint_as_float(f2tf(b * cosf(f1) + a * sinf(f1)));
}

// ---------------------------------------------------------------------------
// Flash attention, tf32 mma.sync. Block = 128 threads (4 warps), 64 q rows.
// Inputs are pre-rounded tf32 -> no cvt in staging/Q-frag paths.
// K tile staged via cp.async (raw), V transposed through registers (raw).
// it reversed so heavy causal blocks launch first.
// ---------------------------------------------------------------------------
#define KS_PAD 68
#define VS_PAD 65
#define SS_PAD 69
#define ATT_SMEM_FLOATS (64*KS_PAD + 64*VS_PAD + 64*SS_PAD + 64*3 + 128*2)

__global__ __launch_bounds__(128) void attn_mma(
    const float* __restrict__ Qb, const float* __restrict__ Kb,
    const float* __restrict__ Vb, float* __restrict__ vals)
{
    extern __shared__ float smf[];
    float* Ks   = smf;                       // [64][68]
    float* Vs   = Ks + 64 * KS_PAD;          // [64][65]  (V transposed: [c][j])
    float* Ss   = Vs + 64 * VS_PAD;          // [64][69]
    float* mrow = Ss + 64 * SS_PAD;          // [64]
    float* lrow = mrow + 64;                 // [64]
    float* crow = lrow + 64;                 // [64]
    float* pmax = crow + 64;                 // [2][64]
    float* psum = pmax + 128;                // [2][64]

    const int h = blockIdx.y;
    const int it = gridDim.x - 1 - blockIdx.x;   // heavy blocks first
    const int tid = threadIdx.x;
    const int w = tid >> 5, lane = tid & 31;
    const int g = lane >> 2, tg = lane & 3;
    const int stripe = w * 16;

    // Q fragments: inputs already tf32; *0.125 is an exact exponent shift
    const float* Qh = Qb + ((size_t)h * T_DIM + it * 64) * HD;
    unsigned qf[8][4];
#pragma unroll
    for (int s = 0; s < 8; s++) {
        int r0 = (stripe + g) * HD, r1 = (stripe + g + 8) * HD;
        qf[s][0] = __float_as_uint(Qh[r0 + s * 8 + tg] * 0.125f);
        qf[s][1] = __float_as_uint(Qh[r1 + s * 8 + tg] * 0.125f);
        qf[s][2] = __float_as_uint(Qh[r0 + s * 8 + tg + 4] * 0.125f);
        qf[s][3] = __float_as_uint(Qh[r1 + s * 8 + tg + 4] * 0.125f);
    }

    float of[8][4];
#pragma unroll
    for (int nt = 0; nt < 8; nt++)
#pragma unroll
        for (int r = 0; r < 4; r++) of[nt][r] = 0.f;

    if (tid < 64) { mrow[tid] = -INFINITY; lrow[tid] = 0.f; }

    const float* Kh = Kb + (size_t)h * T_DIM * HD;
    const float* Vh = Vb + (size_t)h * T_DIM * HD;

    const int row = tid & 63, half = tid >> 6;
    const int cbeg = half * 32;

    for (int jt = 0; jt <= it; jt++) {
        __syncthreads();   // (a) prev-iter reads of Ks/Vs/Ss done; init visible

        // --- K tile via cp.async (raw; rows are 16B-aligned: 68*4=272B) ---
#pragma unroll
        for (int p = 0; p < 8; p++) {
            int idx = tid + p * 128;
            int j = idx >> 4, c4 = idx & 15;
            CP_ASYNC16(smem_u32(&Ks[j * KS_PAD + 4 * c4]),
                       &Kh[(size_t)(jt * 64 + j) * HD + 4 * c4]);
        }
        CP_COMMIT();
        // --- V tile transposed through registers (raw, overlaps K DMA) ---
#pragma unroll
        for (int p = 0; p < 8; p++) {
            int idx = tid + p * 128;
            int j = idx >> 4, c4 = idx & 15;
            float4 vf = *(const float4*)&Vh[(size_t)(jt * 64 + j) * HD + 4 * c4];
            Vs[(4 * c4 + 0) * VS_PAD + j] = vf.x;
            Vs[(4 * c4 + 1) * VS_PAD + j] = vf.y;
            Vs[(4 * c4 + 2) * VS_PAD + j] = vf.z;
            Vs[(4 * c4 + 3) * VS_PAD + j] = vf.w;
        }
        asm volatile("cp.async.wait_group 0;" ::: "memory");
        __syncthreads();   // (b) tiles ready

        // --- S = Q K^T (already scaled) ---
#pragma unroll
        for (int nt = 0; nt < 8; nt++) {
            float sf[4] = {0.f, 0.f, 0.f, 0.f};
#pragma unroll
            for (int s = 0; s < 8; s++) {
                unsigned b0 = __float_as_uint(Ks[(nt * 8 + g) * KS_PAD + s * 8 + tg]);
                unsigned b1 = __float_as_uint(Ks[(nt * 8 + g) * KS_PAD + s * 8 + tg + 4]);
                mma8(sf, qf[s], b0, b1);
            }
            int r0 = stripe + g, col = nt * 8 + 2 * tg;
            Ss[r0 * SS_PAD + col]           = sf[0];
            Ss[r0 * SS_PAD + col + 1]       = sf[1];
            Ss[(r0 + 8) * SS_PAD + col]     = sf[2];
            Ss[(r0 + 8) * SS_PAD + col + 1] = sf[3];
        }
        __syncthreads();   // (c) S ready

        // --- softmax: 128 threads, half-row each; fast path when unmasked ---
        float lmax = -INFINITY;
        if (jt < it) {
#pragma unroll
            for (int jj = 0; jj < 32; jj++)
                lmax = fmaxf(lmax, Ss[row * SS_PAD + cbeg + jj]);
        } else {
#pragma unroll
            for (int jj = 0; jj < 32; jj++) {
                int c = cbeg + jj;
                if (c <= row) lmax = fmaxf(lmax, Ss[row * SS_PAD + c]);
            }
        }
        pmax[half * 64 + row] = lmax;
        __syncthreads();   // (d) partial maxima ready

        float mold = mrow[row];
        float mnew = fmaxf(mold, fmaxf(pmax[row], pmax[64 + row]));
        float corrv = __expf(mold - mnew);
        float ls = 0.f;
        if (jt < it) {
#pragma unroll
            for (int jj = 0; jj < 32; jj++) {
                int c = cbeg + jj;
                float p = __expf(Ss[row * SS_PAD + c] - mnew);
                ls += p;
                Ss[row * SS_PAD + c] = __uint_as_float(f2tf(p));
            }
        } else {
#pragma unroll
            for (int jj = 0; jj < 32; jj++) {
                int c = cbeg + jj;
                float p = (c <= row) ? __expf(Ss[row * SS_PAD + c] - mnew) : 0.f;
                ls += p;
                Ss[row * SS_PAD + c] = __uint_as_float(f2tf(p));
            }
        }
        psum[half * 64 + row] = ls;
        if (half == 0) crow[row] = corrv;
        __syncthreads();   // (e) P, corr, partial sums ready

        if (half == 0) {
            lrow[row] = lrow[row] * corrv + psum[row] + psum[64 + row];
            mrow[row] = mnew;
        }

        // --- rescale O, then O += P V ---
        float cr0 = crow[stripe + g], cr1 = crow[stripe + g + 8];
#pragma unroll
        for (int nt = 0; nt < 8; nt++) {
            of[nt][0] *= cr0; of[nt][1] *= cr0;
            of[nt][2] *= cr1; of[nt][3] *= cr1;
        }
#pragma unroll
        for (int s = 0; s < 8; s++) {
            unsigned af[4];
            af[0] = __float_as_uint(Ss[(stripe + g) * SS_PAD + s * 8 + tg]);
            af[1] = __float_as_uint(Ss[(stripe + g + 8) * SS_PAD + s * 8 + tg]);
            af[2] = __float_as_uint(Ss[(stripe + g) * SS_PAD + s * 8 + tg + 4]);
            af[3] = __float_as_uint(Ss[(stripe + g + 8) * SS_PAD + s * 8 + tg + 4]);
#pragma unroll
            for (int nt = 0; nt < 8; nt++) {
                unsigned b0 = __float_as_uint(Vs[(nt * 8 + g) * VS_PAD + s * 8 + tg]);
                unsigned b1 = __float_as_uint(Vs[(nt * 8 + g) * VS_PAD + s * 8 + tg + 4]);
                mma8(of[nt], af, b0, b1);
            }
        }
    }

    // --- epilogue: O /= l, write [t][h*64+c] ---
    __syncthreads();
    if (tid < 64) crow[tid] = 1.f / lrow[tid];
    __syncthreads();
    float i0 = crow[stripe + g], i1 = crow[stripe + g + 8];
    int qi0 = it * 64 + stripe + g;
#pragma unroll
    for (int nt = 0; nt < 8; nt++) {
        int col = h * 64 + nt * 8 + 2 * tg;
        *(float2*)&vals[(size_t)qi0 * D_DIM + col] =
            make_float2(of[nt][0] * i0, of[nt][1] * i0);
        *(float2*)&vals[(size_t)(qi0 + 8) * D_DIM + col] =
            make_float2(of[nt][2] * i1, of[nt][3] * i1);
    }
}

// ---------------------------------------------------------------------------
extern "C" void kernel_launch(void* const* d_in, const int* in_sizes, int n_in,
                              void* d_out, int out_size)
{
    const float* q     = (const float*)d_in[0];
    const float* k     = (const float*)d_in[1];
    const float* v     = (const float*)d_in[2];
    // d_in[3] = mask (causal, static -> unused)
    const float* freqs = (const float*)d_in[4];
    const float* wq    = (const float*)d_in[5];
    const float* wk    = (const float*)d_in[6];
    const float* wv    = (const float*)d_in[7];
    const float* wo    = (const float*)d_in[8];
    float* out = (float*)d_out;

    float *gq, *gk, *gv, *gvals;
    cudaGetSymbolAddress((void**)&gq, g_Q);
    cudaGetSymbolAddress((void**)&gk, g_K);
    cudaGetSymbolAddress((void**)&gv, g_V);
    cudaGetSymbolAddress((void**)&gvals, g_vals);

    const int att_smem  = ATT_SMEM_FLOATS * sizeof(float);    // 53504 B
    const int gemm_smem = GEMM_SMEM_FLOATS * sizeof(float);   // 73728 B
    cudaFuncSetAttribute(attn_mma, cudaFuncAttributeMaxDynamicSharedMemorySize, att_smem);
    cudaFuncSetAttribute(gemm_tf32, cudaFuncAttributeMaxDynamicSharedMemorySize, gemm_smem);

    dim3 ggrid(D_DIM / 128, T_DIM / 128);  // (8, 32)

    gemm_tf32<<<ggrid, 256, gemm_smem>>>(q, wq, gq, T_DIM, D_DIM, D_DIM, 1);
    gemm_tf32<<<ggrid, 256, gemm_smem>>>(k, wk, gk, T_DIM, D_DIM, D_DIM, 1);
    gemm_tf32<<<ggrid, 256, gemm_smem>>>(v, wv, gv, T_DIM, D_DIM, D_DIM, 1);

    rope_kernel<<<dim3(NH * T_DIM * 16 / 256, 3), 256>>>(gq, gk, gv, freqs);

    attn_mma<<<dim3(T_DIM / 64, NH), 128, att_smem>>>(gq, gk, gv, gvals);

    gemm_tf32<<<ggrid, 256, gemm_smem>>>(gvals, wo, out, T_DIM, D_DIM, D_DIM, 0);
}

// round 13
// speedup vs baseline: 1.4786x; 1.3627x over previous
#include <cuda_runtime.h>
#include <cuda_fp16.h>
#include <math.h>
#include <stdint.h>

#define T_DIM 4096
#define D_DIM 1024
#define NH    16
#define HD    64
#define L_ROT 32

// Scratch (no allocations allowed -> __device__ globals)
__device__ __half g_Q[NH * T_DIM * HD];
__device__ __half g_K[NH * T_DIM * HD];
__device__ __half g_V[NH * T_DIM * HD];
__device__ float  g_vals[T_DIM * D_DIM];

// ---------------------------------------------------------------------------
// helpers
// ---------------------------------------------------------------------------
__device__ __forceinline__ uint32_t smem_u32(const void* p) {
    uint32_t a;
    asm("{ .reg .u64 t; cvta.to.shared.u64 t, %1; cvt.u32.u64 %0, t; }" : "=r"(a) : "l"(p));
    return a;
}

__device__ __forceinline__ unsigned h2u(__half2 h) { return *(unsigned*)&h; }

// D += A(16x16, row) * B(16x8, col);  f16 in, f32 accum
__device__ __forceinline__ void mma16(float* d, const unsigned* a, unsigned b0, unsigned b1) {
    asm volatile(
        "mma.sync.aligned.m16n8k16.row.col.f32.f16.f16.f32 "
        "{%0,%1,%2,%3}, {%4,%5,%6,%7}, {%8,%9}, {%0,%1,%2,%3};"
        : "+f"(d[0]), "+f"(d[1]), "+f"(d[2]), "+f"(d[3])
        : "r"(a[0]), "r"(a[1]), "r"(a[2]), "r"(a[3]), "r"(b0), "r"(b1));
}

#define CP_ASYNC16(dst_u32, src_ptr) \
    asm volatile("cp.async.cg.shared.global [%0], [%1], 16;" :: "r"(dst_u32), "l"(src_ptr))
#define CP_COMMIT() asm volatile("cp.async.commit_group;" ::: "memory")

// ---------------------------------------------------------------------------
// fp16 GEMM via mma.sync m16n8k16.  C = A (MxK row-major, f32) * B^T (NxK, f32)
// mode 0: C[m*N + n] (fp32)            -- final projection output
// mode 1: C[((n>>6)*M + m)*64 + (n&63)] per-head layout, __half output
// BM=BN=128, BK=32, 256 threads, warp grid 2(M)x4(N), warp tile 64x32.
// SMEM half, row pad 40 (frag loads conflict-free: bank=(20g+8s+tg)%32).
// ---------------------------------------------------------------------------
#define GAPAD 40

__global__ __launch_bounds__(256) void gemm_f16(
    const float* __restrict__ A, const float* __restrict__ B,
    void* __restrict__ Cout, int M, int N, int K, int mode)
{
    __shared__ __half As[2][128 * GAPAD];
    __shared__ __half Bs[2][128 * GAPAD];

    const int tid = threadIdx.x;
    const int bm = blockIdx.y * 128;
    const int bn = blockIdx.x * 128;
    const int w = tid >> 5, lane = tid & 31;
    const int g = lane >> 2, tg = lane & 3;
    const int wm = (w >> 2) * 64;   // warp M offset (0 or 64)
    const int wn = (w & 3) * 32;    // warp N offset (0..96)

    const int lr = tid >> 1;          // 0..127: row
    const int lc = (tid & 1) * 16;    // 0 or 16: col base (16 f32 per thread)

    const float* arow = A + (size_t)(bm + lr) * K + lc;
    const float* brow = B + (size_t)(bn + lr) * K + lc;

    float cf[4][4][4];
#pragma unroll
    for (int mt = 0; mt < 4; mt++)
#pragma unroll
        for (int nt = 0; nt < 4; nt++)
#pragma unroll
            for (int r = 0; r < 4; r++) cf[mt][nt][r] = 0.f;

    // prefetch chunk 0 into registers
    float4 av[4], bv[4];
#pragma unroll
    for (int s2 = 0; s2 < 4; s2++) {
        av[s2] = *(const float4*)(arow + s2 * 4);
        bv[s2] = *(const float4*)(brow + s2 * 4);
    }

    const int NC = K / 32;
    for (int c = 0; c < NC; c++) {
        const int buf = c & 1;
        // STS current chunk as half (2 x 16B per matrix per thread)
        {
            __half2 ah[8], bh[8];
#pragma unroll
            for (int s2 = 0; s2 < 4; s2++) {
                ah[2 * s2]     = __floats2half2_rn(av[s2].x, av[s2].y);
                ah[2 * s2 + 1] = __floats2half2_rn(av[s2].z, av[s2].w);
                bh[2 * s2]     = __floats2half2_rn(bv[s2].x, bv[s2].y);
                bh[2 * s2 + 1] = __floats2half2_rn(bv[s2].z, bv[s2].w);
            }
            *(uint4*)&As[buf][lr * GAPAD + lc]     = *(uint4*)&ah[0];
            *(uint4*)&As[buf][lr * GAPAD + lc + 8] = *(uint4*)&ah[4];
            *(uint4*)&Bs[buf][lr * GAPAD + lc]     = *(uint4*)&bh[0];
            *(uint4*)&Bs[buf][lr * GAPAD + lc + 8] = *(uint4*)&bh[4];
        }
        // prefetch next chunk
        if (c + 1 < NC) {
            const float* ap = arow + (c + 1) * 32;
            const float* bp = brow + (c + 1) * 32;
#pragma unroll
            for (int s2 = 0; s2 < 4; s2++) {
                av[s2] = *(const float4*)(ap + s2 * 4);
                bv[s2] = *(const float4*)(bp + s2 * 4);
            }
        }
        __syncthreads();

        const __half* As_ = As[buf];
        const __half* Bs_ = Bs[buf];
#pragma unroll
        for (int s = 0; s < 2; s++) {
            unsigned af[4][4];
#pragma unroll
            for (int mt = 0; mt < 4; mt++) {
                int r = wm + mt * 16;
                af[mt][0] = *(const unsigned*)&As_[(r + g) * GAPAD + s * 16 + 2 * tg];
                af[mt][1] = *(const unsigned*)&As_[(r + g + 8) * GAPAD + s * 16 + 2 * tg];
                af[mt][2] = *(const unsigned*)&As_[(r + g) * GAPAD + s * 16 + 2 * tg + 8];
                af[mt][3] = *(const unsigned*)&As_[(r + g + 8) * GAPAD + s * 16 + 2 * tg + 8];
            }
#pragma unroll
            for (int nt = 0; nt < 4; nt++) {
                int cn = wn + nt * 8 + g;
                unsigned b0 = *(const unsigned*)&Bs_[cn * GAPAD + s * 16 + 2 * tg];
                unsigned b1 = *(const unsigned*)&Bs_[cn * GAPAD + s * 16 + 2 * tg + 8];
#pragma unroll
                for (int mt = 0; mt < 4; mt++) mma16(cf[mt][nt], af[mt], b0, b1);
            }
        }
        __syncthreads();
    }

#pragma unroll
    for (int mt = 0; mt < 4; mt++) {
        int m = bm + wm + mt * 16 + g;
#pragma unroll
        for (int nt = 0; nt < 4; nt++) {
            int n = bn + wn + nt * 8 + 2 * tg;
            if (mode == 0) {
                float* C = (float*)Cout;
                *(float2*)&C[(size_t)m * N + n] =
                    make_float2(cf[mt][nt][0], cf[mt][nt][1]);
                *(float2*)&C[(size_t)(m + 8) * N + n] =
                    make_float2(cf[mt][nt][2], cf[mt][nt][3]);
            } else {
                __half* C = (__half*)Cout;
                int h = n >> 6, d = n & 63;
                *(__half2*)&C[(size_t)(h * M + m) * 64 + d] =
                    __floats2half2_rn(cf[mt][nt][0], cf[mt][nt][1]);
                *(__half2*)&C[(size_t)(h * M + m + 8) * 64 + d] =
                    __floats2half2_rn(cf[mt][nt][2], cf[mt][nt][3]);
            }
        }
    }
}

// ---------------------------------------------------------------------------
// fused RoPE on half buffers: first 32 dims of each head (ROT_SCALE = 1)
// ---------------------------------------------------------------------------
__global__ void rope_kernel(__half* __restrict__ bq, __half* __restrict__ bk,
                            __half* __restrict__ bv, const float* __restrict__ freqs)
{
    int idx = blockIdx.x * blockDim.x + threadIdx.x;  // NH*T_DIM*16 total
    int p = idx & 15;
    int t = (idx >> 4) & (T_DIM - 1);
    int h = idx >> 16;
    if (h >= NH) return;
    __half* buf = (blockIdx.y == 0) ? bq : (blockIdx.y == 1) ? bk : bv;
    __half* x = buf + ((size_t)h * T_DIM + t) * HD;
    float a = __half2float(x[p]);
    float b = __half2float(x[p + 16]);
    float f0 = freqs[t * L_ROT + p];
    float f1 = freqs[t * L_ROT + p + 16];
    x[p]      = __float2half_rn(a * cosf(f0) - b * sinf(f0));
    x[p + 16] = __float2half_rn(b * cosf(f1) + a * sinf(f1));
}

// ---------------------------------------------------------------------------
// Flash attention, fp16 mma.sync m16n8k16. Block = 128 threads, 64 q rows.
// K [j][64] half pad 72 (b-frags CF), V^T [c][j] half pad 72, P [i][j] half
// pad 72 (a-frags CF), S scores f32 pad 69 (softmax CF).
// it reversed so heavy causal blocks launch first.
// ---------------------------------------------------------------------------
#define KPADH 72
#define SS_PAD 69

__global__ __launch_bounds__(128) void attn_mma(
    const __half* __restrict__ Qb, const __half* __restrict__ Kb,
    const __half* __restrict__ Vb, float* __restrict__ vals)
{
    __shared__ __half Ks[64 * KPADH];
    __shared__ __half Vs[64 * KPADH];     // V transposed: [c][j]
    __shared__ __half Ps[64 * KPADH];
    __shared__ float  Ss[64 * SS_PAD];
    __shared__ float  mrow[64], lrow[64], crow[64];
    __shared__ float  pmax[128], psum[128];

    const int h = blockIdx.y;
    const int it = gridDim.x - 1 - blockIdx.x;   // heavy blocks first
    const int tid = threadIdx.x;
    const int w = tid >> 5, lane = tid & 31;
    const int g = lane >> 2, tg = lane & 3;
    const int stripe = w * 16;

    // Q fragments (half2 pairs), scaled by 0.125 (exact exponent shift)
    const __half2* Qh2 = (const __half2*)(Qb + ((size_t)h * T_DIM + it * 64) * HD);
    const __half2 qsc = __floats2half2_rn(0.125f, 0.125f);
    unsigned qf[4][4];
#pragma unroll
    for (int s = 0; s < 4; s++) {
        int r0 = (stripe + g) * 32, r1 = (stripe + g + 8) * 32;  // half2 row stride 32
        qf[s][0] = h2u(__hmul2(Qh2[r0 + s * 8 + tg], qsc));
        qf[s][1] = h2u(__hmul2(Qh2[r1 + s * 8 + tg], qsc));
        qf[s][2] = h2u(__hmul2(Qh2[r0 + s * 8 + tg + 4], qsc));
        qf[s][3] = h2u(__hmul2(Qh2[r1 + s * 8 + tg + 4], qsc));
    }

    float of[8][4];
#pragma unroll
    for (int nt = 0; nt < 8; nt++)
#pragma unroll
        for (int r = 0; r < 4; r++) of[nt][r] = 0.f;

    if (tid < 64) { mrow[tid] = -INFINITY; lrow[tid] = 0.f; }

    const __half* Kh = Kb + (size_t)h * T_DIM * HD;
    const __half* Vh = Vb + (size_t)h * T_DIM * HD;

    const int row = tid & 63, half_ = tid >> 6;
    const int cbeg = half_ * 32;

    for (int jt = 0; jt <= it; jt++) {
        __syncthreads();   // (a) prev-iter reads done; init visible

        // --- K tile via cp.async (8 halves = 16B per op; rows 144B aligned) ---
#pragma unroll
        for (int p = 0; p < 4; p++) {
            int idx = tid + p * 128;
            int j = idx >> 3, c8 = idx & 7;
            CP_ASYNC16(smem_u32(&Ks[j * KPADH + c8 * 8]),
                       Kh + (size_t)(jt * 64 + j) * HD + c8 * 8);
        }
        CP_COMMIT();
        // --- V tile transposed through registers (overlaps K DMA) ---
#pragma unroll
        for (int p = 0; p < 4; p++) {
            int idx = tid + p * 128;
            int j = idx >> 3, c8 = idx & 7;
            uint4 vraw = *(const uint4*)(Vh + (size_t)(jt * 64 + j) * HD + c8 * 8);
            const __half* vh = (const __half*)&vraw;
#pragma unroll
            for (int q = 0; q < 8; q++)
                Vs[(c8 * 8 + q) * KPADH + j] = vh[q];
        }
        asm volatile("cp.async.wait_group 0;" ::: "memory");
        __syncthreads();   // (b) tiles ready

        // --- S = Q K^T (already scaled) ---
#pragma unroll
        for (int nt = 0; nt < 8; nt++) {
            float sf[4] = {0.f, 0.f, 0.f, 0.f};
#pragma unroll
            for (int s = 0; s < 4; s++) {
                unsigned b0 = *(const unsigned*)&Ks[(nt * 8 + g) * KPADH + s * 16 + 2 * tg];
                unsigned b1 = *(const unsigned*)&Ks[(nt * 8 + g) * KPADH + s * 16 + 2 * tg + 8];
                mma16(sf, qf[s], b0, b1);
            }
            int r0 = stripe + g, col = nt * 8 + 2 * tg;
            Ss[r0 * SS_PAD + col]           = sf[0];
            Ss[r0 * SS_PAD + col + 1]       = sf[1];
            Ss[(r0 + 8) * SS_PAD + col]     = sf[2];
            Ss[(r0 + 8) * SS_PAD + col + 1] = sf[3];
        }
        __syncthreads();   // (c) S ready

        // --- softmax: 128 threads, half-row each; fast path when unmasked ---
        float lmax = -INFINITY;
        if (jt < it) {
#pragma unroll
            for (int jj = 0; jj < 32; jj++)
                lmax = fmaxf(lmax, Ss[row * SS_PAD + cbeg + jj]);
        } else {
#pragma unroll
            for (int jj = 0; jj < 32; jj++) {
                int c = cbeg + jj;
                if (c <= row) lmax = fmaxf(lmax, Ss[row * SS_PAD + c]);
            }
        }
        pmax[half_ * 64 + row] = lmax;
        __syncthreads();   // (d) partial maxima ready

        float mold = mrow[row];
        float mnew = fmaxf(mold, fmaxf(pmax[row], pmax[64 + row]));
        float corrv = __expf(mold - mnew);
        float ls = 0.f;
        if (jt < it) {
#pragma unroll
            for (int jj2 = 0; jj2 < 16; jj2++) {
                int c = cbeg + 2 * jj2;
                float p0 = __expf(Ss[row * SS_PAD + c] - mnew);
                float p1 = __expf(Ss[row * SS_PAD + c + 1] - mnew);
                ls += p0 + p1;
                *(__half2*)&Ps[row * KPADH + c] = __floats2half2_rn(p0, p1);
            }
        } else {
#pragma unroll
            for (int jj2 = 0; jj2 < 16; jj2++) {
                int c = cbeg + 2 * jj2;
                float p0 = (c <= row)     ? __expf(Ss[row * SS_PAD + c] - mnew)     : 0.f;
                float p1 = (c + 1 <= row) ? __expf(Ss[row * SS_PAD + c + 1] - mnew) : 0.f;
                ls += p0 + p1;
                *(__half2*)&Ps[row * KPADH + c] = __floats2half2_rn(p0, p1);
            }
        }
        psum[half_ * 64 + row] = ls;
        if (half_ == 0) crow[row] = corrv;
        __syncthreads();   // (e) P, corr, partial sums ready

        if (half_ == 0) {
            lrow[row] = lrow[row] * corrv + psum[row] + psum[64 + row];
            mrow[row] = mnew;
        }

        // --- rescale O, then O += P V ---
        float cr0 = crow[stripe + g], cr1 = crow[stripe + g + 8];
#pragma unroll
        for (int nt = 0; nt < 8; nt++) {
            of[nt][0] *= cr0; of[nt][1] *= cr0;
            of[nt][2] *= cr1; of[nt][3] *= cr1;
        }
#pragma unroll
        for (int s = 0; s < 4; s++) {
            unsigned af[4];
            af[0] = *(const unsigned*)&Ps[(stripe + g) * KPADH + s * 16 + 2 * tg];
            af[1] = *(const unsigned*)&Ps[(stripe + g + 8) * KPADH + s * 16 + 2 * tg];
            af[2] = *(const unsigned*)&Ps[(stripe + g) * KPADH + s * 16 + 2 * tg + 8];
            af[3] = *(const unsigned*)&Ps[(stripe + g + 8) * KPADH + s * 16 + 2 * tg + 8];
#pragma unroll
            for (int nt = 0; nt < 8; nt++) {
                unsigned b0 = *(const unsigned*)&Vs[(nt * 8 + g) * KPADH + s * 16 + 2 * tg];
                unsigned b1 = *(const unsigned*)&Vs[(nt * 8 + g) * KPADH + s * 16 + 2 * tg + 8];
                mma16(of[nt], af, b0, b1);
            }
        }
    }

    // --- epilogue: O /= l, write [t][h*64+c] (f32) ---
    __syncthreads();
    if (tid < 64) crow[tid] = 1.f / lrow[tid];
    __syncthreads();
    float i0 = crow[stripe + g], i1 = crow[stripe + g + 8];
    int qi0 = it * 64 + stripe + g;
#pragma unroll
    for (int nt = 0; nt < 8; nt++) {
        int col = h * 64 + nt * 8 + 2 * tg;
        *(float2*)&vals[(size_t)qi0 * D_DIM + col] =
            make_float2(of[nt][0] * i0, of[nt][1] * i0);
        *(float2*)&vals[(size_t)(qi0 + 8) * D_DIM + col] =
            make_float2(of[nt][2] * i1, of[nt][3] * i1);
    }
}

// ---------------------------------------------------------------------------
extern "C" void kernel_launch(void* const* d_in, const int* in_sizes, int n_in,
                              void* d_out, int out_size)
{
    const float* q     = (const float*)d_in[0];
    const float* k     = (const float*)d_in[1];
    const float* v     = (const float*)d_in[2];
    // d_in[3] = mask (causal, static -> unused)
    const float* freqs = (const float*)d_in[4];
    const float* wq    = (const float*)d_in[5];
    const float* wk    = (const float*)d_in[6];
    const float* wv    = (const float*)d_in[7];
    const float* wo    = (const float*)d_in[8];
    float* out = (float*)d_out;

    __half *gq, *gk, *gv;
    float *gvals;
    cudaGetSymbolAddress((void**)&gq, g_Q);
    cudaGetSymbolAddress((void**)&gk, g_K);
    cudaGetSymbolAddress((void**)&gv, g_V);
    cudaGetSymbolAddress((void**)&gvals, g_vals);

    dim3 ggrid(D_DIM / 128, T_DIM / 128);  // (8, 32)

    gemm_f16<<<ggrid, 256>>>(q, wq, gq, T_DIM, D_DIM, D_DIM, 1);
    gemm_f16<<<ggrid, 256>>>(k, wk, gk, T_DIM, D_DIM, D_DIM, 1);
    gemm_f16<<<ggrid, 256>>>(v, wv, gv, T_DIM, D_DIM, D_DIM, 1);

    rope_kernel<<<dim3(NH * T_DIM * 16 / 256, 3), 256>>>(gq, gk, gv, freqs);

    attn_mma<<<dim3(T_DIM / 64, NH), 128>>>(gq, gk, gv, gvals);

    gemm_f16<<<ggrid, 256>>>(gvals, wo, out, T_DIM, D_DIM, D_DIM, 0);
}

// round 15
// speedup vs baseline: 1.8925x; 1.2800x over previous
#include <cuda_runtime.h>
#include <cuda_fp16.h>
#include <math.h>
#include <stdint.h>

#define T_DIM 4096
#define D_DIM 1024
#define NH    16
#define HD    64
#define L_ROT 32

// Scratch (no allocations allowed -> __device__ globals)
__device__ __half g_Q[NH * T_DIM * HD];
__device__ __half g_K[NH * T_DIM * HD];
__device__ __half g_V[NH * T_DIM * HD];
__device__ float  g_vals[T_DIM * D_DIM];

// ---------------------------------------------------------------------------
// helpers
// ---------------------------------------------------------------------------
__device__ __forceinline__ uint32_t smem_u32(const void* p) {
    uint32_t a;
    asm("{ .reg .u64 t; cvta.to.shared.u64 t, %1; cvt.u32.u64 %0, t; }" : "=r"(a) : "l"(p));
    return a;
}

__device__ __forceinline__ unsigned h2u(__half2 h) { return *(unsigned*)&h; }

// D += A(16x16, row) * B(16x8, col);  f16 in, f32 accum
__device__ __forceinline__ void mma16(float* d, const unsigned* a, unsigned b0, unsigned b1) {
    asm volatile(
        "mma.sync.aligned.m16n8k16.row.col.f32.f16.f16.f32 "
        "{%0,%1,%2,%3}, {%4,%5,%6,%7}, {%8,%9}, {%0,%1,%2,%3};"
        : "+f"(d[0]), "+f"(d[1]), "+f"(d[2]), "+f"(d[3])
        : "r"(a[0]), "r"(a[1]), "r"(a[2]), "r"(a[3]), "r"(b0), "r"(b1));
}

#define CP_ASYNC16(dst_u32, src_ptr) \
    asm volatile("cp.async.cg.shared.global [%0], [%1], 16;" :: "r"(dst_u32), "l"(src_ptr))
#define CP_COMMIT() asm volatile("cp.async.commit_group;" ::: "memory")

// ---------------------------------------------------------------------------
// fp16 GEMM via mma.sync m16n8k16.  C = A (MxK row-major, f32) * B^T (NxK, f32)
// mode 0: C[m*N + n] (fp32)            -- final projection output
// mode 1: C[((n>>6)*M + m)*64 + (n&63)] per-head layout, __half output
// BM=BN=128, BK=32, 256 threads, warp grid 2(M)x4(N), warp tile 64x32.
// ---------------------------------------------------------------------------
#define GAPAD 40

__global__ __launch_bounds__(256) void gemm_f16(
    const float* __restrict__ A, const float* __restrict__ B,
    void* __restrict__ Cout, int M, int N, int K, int mode)
{
    __shared__ __half As[2][128 * GAPAD];
    __shared__ __half Bs[2][128 * GAPAD];

    const int tid = threadIdx.x;
    const int bm = blockIdx.y * 128;
    const int bn = blockIdx.x * 128;
    const int w = tid >> 5, lane = tid & 31;
    const int g = lane >> 2, tg = lane & 3;
    const int wm = (w >> 2) * 64;
    const int wn = (w & 3) * 32;

    const int lr = tid >> 1;
    const int lc = (tid & 1) * 16;

    const float* arow = A + (size_t)(bm + lr) * K + lc;
    const float* brow = B + (size_t)(bn + lr) * K + lc;

    float cf[4][4][4];
#pragma unroll
    for (int mt = 0; mt < 4; mt++)
#pragma unroll
        for (int nt = 0; nt < 4; nt++)
#pragma unroll
            for (int r = 0; r < 4; r++) cf[mt][nt][r] = 0.f;

    float4 av[4], bv[4];
#pragma unroll
    for (int s2 = 0; s2 < 4; s2++) {
        av[s2] = *(const float4*)(arow + s2 * 4);
        bv[s2] = *(const float4*)(brow + s2 * 4);
    }

    const int NC = K / 32;
    for (int c = 0; c < NC; c++) {
        const int buf = c & 1;
        {
            __half2 ah[8], bh[8];
#pragma unroll
            for (int s2 = 0; s2 < 4; s2++) {
                ah[2 * s2]     = __floats2half2_rn(av[s2].x, av[s2].y);
                ah[2 * s2 + 1] = __floats2half2_rn(av[s2].z, av[s2].w);
                bh[2 * s2]     = __floats2half2_rn(bv[s2].x, bv[s2].y);
                bh[2 * s2 + 1] = __floats2half2_rn(bv[s2].z, bv[s2].w);
            }
            *(uint4*)&As[buf][lr * GAPAD + lc]     = *(uint4*)&ah[0];
            *(uint4*)&As[buf][lr * GAPAD + lc + 8] = *(uint4*)&ah[4];
            *(uint4*)&Bs[buf][lr * GAPAD + lc]     = *(uint4*)&bh[0];
            *(uint4*)&Bs[buf][lr * GAPAD + lc + 8] = *(uint4*)&bh[4];
        }
        if (c + 1 < NC) {
            const float* ap = arow + (c + 1) * 32;
            const float* bp = brow + (c + 1) * 32;
#pragma unroll
            for (int s2 = 0; s2 < 4; s2++) {
                av[s2] = *(const float4*)(ap + s2 * 4);
                bv[s2] = *(const float4*)(bp + s2 * 4);
            }
        }
        __syncthreads();

        const __half* As_ = As[buf];
        const __half* Bs_ = Bs[buf];
#pragma unroll
        for (int s = 0; s < 2; s++) {
            unsigned af[4][4];
#pragma unroll
            for (int mt = 0; mt < 4; mt++) {
                int r = wm + mt * 16;
                af[mt][0] = *(const unsigned*)&As_[(r + g) * GAPAD + s * 16 + 2 * tg];
                af[mt][1] = *(const unsigned*)&As_[(r + g + 8) * GAPAD + s * 16 + 2 * tg];
                af[mt][2] = *(const unsigned*)&As_[(r + g) * GAPAD + s * 16 + 2 * tg + 8];
                af[mt][3] = *(const unsigned*)&As_[(r + g + 8) * GAPAD + s * 16 + 2 * tg + 8];
            }
#pragma unroll
            for (int nt = 0; nt < 4; nt++) {
                int cn = wn + nt * 8 + g;
                unsigned b0 = *(const unsigned*)&Bs_[cn * GAPAD + s * 16 + 2 * tg];
                unsigned b1 = *(const unsigned*)&Bs_[cn * GAPAD + s * 16 + 2 * tg + 8];
#pragma unroll
                for (int mt = 0; mt < 4; mt++) mma16(cf[mt][nt], af[mt], b0, b1);
            }
        }
        __syncthreads();
    }

#pragma unroll
    for (int mt = 0; mt < 4; mt++) {
        int m = bm + wm + mt * 16 + g;
#pragma unroll
        for (int nt = 0; nt < 4; nt++) {
            int n = bn + wn + nt * 8 + 2 * tg;
            if (mode == 0) {
                float* C = (float*)Cout;
                *(float2*)&C[(size_t)m * N + n] =
                    make_float2(cf[mt][nt][0], cf[mt][nt][1]);
                *(float2*)&C[(size_t)(m + 8) * N + n] =
                    make_float2(cf[mt][nt][2], cf[mt][nt][3]);
            } else {
                __half* C = (__half*)Cout;
                int h = n >> 6, d = n & 63;
                *(__half2*)&C[(size_t)(h * M + m) * 64 + d] =
                    __floats2half2_rn(cf[mt][nt][0], cf[mt][nt][1]);
                *(__half2*)&C[(size_t)(h * M + m + 8) * 64 + d] =
                    __floats2half2_rn(cf[mt][nt][2], cf[mt][nt][3]);
            }
        }
    }
}

// ---------------------------------------------------------------------------
// fused RoPE on half buffers: first 32 dims of each head (ROT_SCALE = 1)
// ---------------------------------------------------------------------------
__global__ void rope_kernel(__half* __restrict__ bq, __half* __restrict__ bk,
                            __half* __restrict__ bv, const float* __restrict__ freqs)
{
    int idx = blockIdx.x * blockDim.x + threadIdx.x;
    int p = idx & 15;
    int t = (idx >> 4) & (T_DIM - 1);
    int h = idx >> 16;
    if (h >= NH) return;
    __half* buf = (blockIdx.y == 0) ? bq : (blockIdx.y == 1) ? bk : bv;
    __half* x = buf + ((size_t)h * T_DIM + t) * HD;
    float a = __half2float(x[p]);
    float b = __half2float(x[p + 16]);
    float f0 = freqs[t * L_ROT + p];
    float f1 = freqs[t * L_ROT + p + 16];
    x[p]      = __float2half_rn(a * cosf(f0) - b * sinf(f0));
    x[p + 16] = __float2half_rn(b * cosf(f1) + a * sinf(f1));
}

// ---------------------------------------------------------------------------
// Flash attention, fp16 mma, REGISTER-RESIDENT softmax (FA2 style).
// Block = 128 threads (4 warps), 64 q rows; warp w owns rows [16w,16w+16).
// S accum stays in registers; row stats via tg-quad shuffles; P packs
// directly into PV A-fragments. K/V tiles double-buffered (cp.async + LDG).
// One __syncthreads per j-tile.
// ---------------------------------------------------------------------------
#define KPADH 72

__global__ __launch_bounds__(128) void attn_mma(
    const __half* __restrict__ Qb, const __half* __restrict__ Kb,
    const __half* __restrict__ Vb, float* __restrict__ vals)
{
    __shared__ __half Ks[2][64 * KPADH];
    __shared__ __half Vs[2][64 * KPADH];   // V transposed: [c][j]

    const int h = blockIdx.y;
    const int it = gridDim.x - 1 - blockIdx.x;   // heavy blocks first
    const int tid = threadIdx.x;
    const int w = tid >> 5, lane = tid & 31;
    const int g = lane >> 2, tg = lane & 3;
    const int stripe = w * 16;

    // Q fragments (half2 pairs), scaled by 0.125 (exact exponent shift)
    const __half2* Qh2 = (const __half2*)(Qb + ((size_t)h * T_DIM + it * 64) * HD);
    const __half2 qsc = __floats2half2_rn(0.125f, 0.125f);
    unsigned qf[4][4];
#pragma unroll
    for (int s = 0; s < 4; s++) {
        int r0 = (stripe + g) * 32, r1 = (stripe + g + 8) * 32;
        qf[s][0] = h2u(__hmul2(Qh2[r0 + s * 8 + tg], qsc));
        qf[s][1] = h2u(__hmul2(Qh2[r1 + s * 8 + tg], qsc));
        qf[s][2] = h2u(__hmul2(Qh2[r0 + s * 8 + tg + 4], qsc));
        qf[s][3] = h2u(__hmul2(Qh2[r1 + s * 8 + tg + 4], qsc));
    }

    float of[8][4];
#pragma unroll
    for (int nt = 0; nt < 8; nt++)
#pragma unroll
        for (int r = 0; r < 4; r++) of[nt][r] = 0.f;

    float m0 = -INFINITY, m1 = -INFINITY, l0 = 0.f, l1 = 0.f;

    const __half* Kh = Kb + (size_t)h * T_DIM * HD;
    const __half* Vh = Vb + (size_t)h * T_DIM * HD;

    // V staging index: j fast over lanes -> STS rows hit distinct banks
    const int vj = tid & 63;          // row j
    const int vc8 = tid >> 6;         // 0..1, +2 per p step
    // K staging index
    const int kj = tid >> 3, kc8 = tid & 7;

    // --- prologue: fill buffer 0 with tile 0 ---
    {
#pragma unroll
        for (int p = 0; p < 4; p++) {
            int j = kj + p * 16;
            CP_ASYNC16(smem_u32(&Ks[0][j * KPADH + kc8 * 8]),
                       Kh + (size_t)j * HD + kc8 * 8);
        }
        CP_COMMIT();
#pragma unroll
        for (int p = 0; p < 4; p++) {
            int c8 = vc8 + p * 2;
            uint4 vraw = *(const uint4*)(Vh + (size_t)vj * HD + c8 * 8);
            const __half* vh = (const __half*)&vraw;
#pragma unroll
            for (int q = 0; q < 8; q++)
                Vs[0][(c8 * 8 + q) * KPADH + vj] = vh[q];
        }
        asm volatile("cp.async.wait_group 0;" ::: "memory");
        __syncthreads();
    }

    for (int jt = 0; jt <= it; jt++) {
        const int buf = jt & 1;
        const bool diag = (jt == it);

        // --- prefetch next tile: K via cp.async, V into registers ---
        uint4 vpre[4];
        if (!diag) {
            const __half* Kn = Kh + (size_t)(jt + 1) * 64 * HD;
            const __half* Vn = Vh + (size_t)(jt + 1) * 64 * HD;
#pragma unroll
            for (int p = 0; p < 4; p++) {
                int j = kj + p * 16;
                CP_ASYNC16(smem_u32(&Ks[buf ^ 1][j * KPADH + kc8 * 8]),
                           Kn + (size_t)j * HD + kc8 * 8);
            }
            CP_COMMIT();
#pragma unroll
            for (int p = 0; p < 4; p++) {
                int c8 = vc8 + p * 2;
                vpre[p] = *(const uint4*)(Vn + (size_t)vj * HD + c8 * 8);
            }
        }

        // --- S = Q K^T (scaled); diag: trim to nt < 2w+2 ---
        const int nmax = diag ? (2 * w + 2) : 8;
        float sf[8][4];
#pragma unroll
        for (int nt = 0; nt < 8; nt++) {
            if (nt >= nmax) break;
            sf[nt][0] = sf[nt][1] = sf[nt][2] = sf[nt][3] = 0.f;
#pragma unroll
            for (int s = 0; s < 4; s++) {
                unsigned b0 = *(const unsigned*)&Ks[buf][(nt * 8 + g) * KPADH + s * 16 + 2 * tg];
                unsigned b1 = *(const unsigned*)&Ks[buf][(nt * 8 + g) * KPADH + s * 16 + 2 * tg + 8];
                mma16(sf[nt], qf[s], b0, b1);
            }
        }

        // --- causal mask on diagonal tile (registers) ---
        if (diag) {
            const int i0 = stripe + g, i1 = stripe + g + 8;
#pragma unroll
            for (int nt = 0; nt < 8; nt++) {
                if (nt >= nmax) break;
                int j0 = nt * 8 + 2 * tg;
                if (j0 > i0)     sf[nt][0] = -1e30f;
                if (j0 + 1 > i0) sf[nt][1] = -1e30f;
                if (j0 > i1)     sf[nt][2] = -1e30f;
                if (j0 + 1 > i1) sf[nt][3] = -1e30f;
            }
        }

        // --- row max via tg-quad shuffles ---
        float r0 = -INFINITY, r1 = -INFINITY;
#pragma unroll
        for (int nt = 0; nt < 8; nt++) {
            if (nt >= nmax) break;
            r0 = fmaxf(r0, fmaxf(sf[nt][0], sf[nt][1]));
            r1 = fmaxf(r1, fmaxf(sf[nt][2], sf[nt][3]));
        }
        r0 = fmaxf(r0, __shfl_xor_sync(0xffffffffu, r0, 1));
        r0 = fmaxf(r0, __shfl_xor_sync(0xffffffffu, r0, 2));
        r1 = fmaxf(r1, __shfl_xor_sync(0xffffffffu, r1, 1));
        r1 = fmaxf(r1, __shfl_xor_sync(0xffffffffu, r1, 2));

        const float mn0 = fmaxf(m0, r0), mn1 = fmaxf(m1, r1);
        const float c0 = __expf(m0 - mn0), c1 = __expf(m1 - mn1);

        // --- exp in registers, pack P fragments, partial sums ---
        float ps0 = 0.f, ps1 = 0.f;
        unsigned ph[8][2];
#pragma unroll
        for (int nt = 0; nt < 8; nt++) {
            if (nt >= nmax) break;
            float p0 = __expf(sf[nt][0] - mn0);
            float p1 = __expf(sf[nt][1] - mn0);
            float p2 = __expf(sf[nt][2] - mn1);
            float p3 = __expf(sf[nt][3] - mn1);
            ps0 += p0 + p1; ps1 += p2 + p3;
            ph[nt][0] = h2u(__floats2half2_rn(p0, p1));
            ph[nt][1] = h2u(__floats2half2_rn(p2, p3));
        }
        ps0 += __shfl_xor_sync(0xffffffffu, ps0, 1);
        ps0 += __shfl_xor_sync(0xffffffffu, ps0, 2);
        ps1 += __shfl_xor_sync(0xffffffffu, ps1, 1);
        ps1 += __shfl_xor_sync(0xffffffffu, ps1, 2);
        l0 = l0 * c0 + ps0; m0 = mn0;
        l1 = l1 * c1 + ps1; m1 = mn1;

        // --- rescale O, then O += P V ---
#pragma unroll
        for (int nt = 0; nt < 8; nt++) {
            of[nt][0] *= c0; of[nt][1] *= c0;
            of[nt][2] *= c1; of[nt][3] *= c1;
        }
        const int smax = diag ? (w + 1) : 4;
#pragma unroll
        for (int s = 0; s < 4; s++) {
            if (s >= smax) break;
            unsigned af[4] = { ph[2 * s][0], ph[2 * s][1], ph[2 * s + 1][0], ph[2 * s + 1][1] };
#pragma unroll
            for (int nt = 0; nt < 8; nt++) {
                unsigned b0 = *(const unsigned*)&Vs[buf][(nt * 8 + g) * KPADH + s * 16 + 2 * tg];
                unsigned b1 = *(const unsigned*)&Vs[buf][(nt * 8 + g) * KPADH + s * 16 + 2 * tg + 8];
                mma16(of[nt], af, b0, b1);
            }
        }

        // --- store prefetched V, close the pipeline stage ---
        if (!diag) {
#pragma unroll
            for (int p = 0; p < 4; p++) {
                int c8 = vc8 + p * 2;
                const __half* vh = (const __half*)&vpre[p];
#pragma unroll
                for (int q = 0; q < 8; q++)
                    Vs[buf ^ 1][(c8 * 8 + q) * KPADH + vj] = vh[q];
            }
            asm volatile("cp.async.wait_group 0;" ::: "memory");
            __syncthreads();
        }
    }

    // --- epilogue: O /= l, write [t][h*64+c] (f32) ---
    const float i0 = 1.f / l0, i1 = 1.f / l1;
    const int qi0 = it * 64 + stripe + g;
#pragma unroll
    for (int nt = 0; nt < 8; nt++) {
        int col = h * 64 + nt * 8 + 2 * tg;
        *(float2*)&vals[(size_t)qi0 * D_DIM + col] =
            make_float2(of[nt][0] * i0, of[nt][1] * i0);
        *(float2*)&vals[(size_t)(qi0 + 8) * D_DIM + col] =
            make_float2(of[nt][2] * i1, of[nt][3] * i1);
    }
}

// ---------------------------------------------------------------------------
extern "C" void kernel_launch(void* const* d_in, const int* in_sizes, int n_in,
                              void* d_out, int out_size)
{
    const float* q     = (const float*)d_in[0];
    const float* k     = (const float*)d_in[1];
    const float* v     = (const float*)d_in[2];
    // d_in[3] = mask (causal, static -> unused)
    const float* freqs = (const float*)d_in[4];
    const float* wq    = (const float*)d_in[5];
    const float* wk    = (const float*)d_in[6];
    const float* wv    = (const float*)d_in[7];
    const float* wo    = (const float*)d_in[8];
    float* out = (float*)d_out;

    __half *gq, *gk, *gv;
    float *gvals;
    cudaGetSymbolAddress((void**)&gq, g_Q);
    cudaGetSymbolAddress((void**)&gk, g_K);
    cudaGetSymbolAddress((void**)&gv, g_V);
    cudaGetSymbolAddress((void**)&gvals, g_vals);

    dim3 ggrid(D_DIM / 128, T_DIM / 128);  // (8, 32)

    gemm_f16<<<ggrid, 256>>>(q, wq, gq, T_DIM, D_DIM, D_DIM, 1);
    gemm_f16<<<ggrid, 256>>>(k, wk, gk, T_DIM, D_DIM, D_DIM, 1);
    gemm_f16<<<ggrid, 256>>>(v, wv, gv, T_DIM, D_DIM, D_DIM, 1);

    rope_kernel<<<dim3(NH * T_DIM * 16 / 256, 3), 256>>>(gq, gk, gv, freqs);

    attn_mma<<<dim3(T_DIM / 64, NH), 128>>>(gq, gk, gv, gvals);

    gemm_f16<<<ggrid, 256>>>(gvals, wo, out, T_DIM, D_DIM, D_DIM, 0);
}